// round 8
// baseline (speedup 1.0000x reference)
#include <cuda_runtime.h>
#include <cstdint>

// Embedding gather with L2 bulk-prefetch pipeline.
// idx: [8192] int32, weight: [32000, 512] f32 (2 KB/row), out: [8192, 512] f32
//
// K1: one thread per token issues cp.async.bulk.prefetch.L2.global for its
//     2 KB weight row (fire-and-forget; fills L2 at DRAM burst rate, no
//     SM-side miss-tracking). Exits immediately after issue.
// K2: demand gather (R3 shape: 2048 CTAs x 128 thr, 4 tokens/CTA, MLP=4)
//     runs behind the prefetch wavefront; misses merge with in-flight
//     fills and retire at fill rate.

static constexpr int VEC_PER_ROW    = 128;   // 512 f32 = 128 float4
static constexpr int ROW_BYTES      = 2048;
static constexpr int TOKENS_PER_CTA = 4;
static constexpr int G_THREADS      = 128;

// ---------------- K1: prefetch ----------------
static constexpr int PF_THREADS = 1024;

__global__ void __launch_bounds__(PF_THREADS, 1)
prefetch_rows_kernel(const int* __restrict__ idx,
                     const char* __restrict__ weight,
                     int n_tokens)
{
    const int t = blockIdx.x * PF_THREADS + threadIdx.x;
    if (t >= n_tokens) return;

    const int row = __ldg(&idx[t]);
    const char* src = weight + (long long)row * ROW_BYTES;
    asm volatile("cp.async.bulk.prefetch.L2.global [%0], %1;"
                 :: "l"(src), "r"((uint32_t)ROW_BYTES) : "memory");
}

// ---------------- K2: gather ----------------
__global__ void __launch_bounds__(G_THREADS, 16)
embedding_gather_kernel(const int* __restrict__ idx,
                        const float4* __restrict__ weight,
                        float4* __restrict__ out)
{
    const int tid        = threadIdx.x;            // vec within row
    const int base_token = blockIdx.x * TOKENS_PER_CTA;

    int rows[TOKENS_PER_CTA];
#pragma unroll
    for (int k = 0; k < TOKENS_PER_CTA; k++)
        rows[k] = __ldg(&idx[base_token + k]);

    float4 v[TOKENS_PER_CTA];
#pragma unroll
    for (int k = 0; k < TOKENS_PER_CTA; k++)
        v[k] = __ldg(&weight[(long long)rows[k] * VEC_PER_ROW + tid]);

#pragma unroll
    for (int k = 0; k < TOKENS_PER_CTA; k++)
        out[(long long)(base_token + k) * VEC_PER_ROW + tid] = v[k];
}

extern "C" void kernel_launch(void* const* d_in, const int* in_sizes, int n_in,
                              void* d_out, int out_size)
{
    const int*   idx    = (const int*)d_in[0];    // x: [4, 2048] int32
    const float* weight = (const float*)d_in[1];  // [32000, 512] f32
    float*       out    = (float*)d_out;          // [4, 2048, 512] f32

    const int n_tokens = in_sizes[0];             // 8192

    const int pf_blocks = (n_tokens + PF_THREADS - 1) / PF_THREADS;   // 8
    prefetch_rows_kernel<<<pf_blocks, PF_THREADS>>>(
        idx, (const char*)weight, n_tokens);

    const int g_blocks = n_tokens / TOKENS_PER_CTA;                   // 2048
    embedding_gather_kernel<<<g_blocks, G_THREADS>>>(
        idx, (const float4*)weight, (float4*)out);
}

// round 9
// speedup vs baseline: 2.1505x; 2.1505x over previous
#include <cuda_runtime.h>
#include <cstdint>

// Embedding gather: out[token, :] = weight[idx[token], :]
// idx: [8192] int32, weight: [32000, 512] f32, out: [8192, 512] f32
//
// At the chip floor: cold-L2 compulsory-miss gather capped by L2 MSHR
// recycle (45/LTS x 128B x 184 / ~1040cyc = ~1.83 TB/s). Shape: one full
// wave (2048 CTAs x 128 thr, 16/SM), 4 tokens/CTA, MLP=4.
// Micro-opts: idx as one LDG.128 (int4), weight via ld.global.cg
// (L2-only; skip useless L1 allocation of never-reused lines).

static constexpr int VEC_PER_ROW    = 128;  // 512 f32 = 128 float4
static constexpr int TOKENS_PER_CTA = 4;
static constexpr int THREADS        = 128;

__global__ void __launch_bounds__(THREADS, 16)
embedding_gather_kernel(const int4* __restrict__ idx4,
                        const float4* __restrict__ weight,
                        float4* __restrict__ out)
{
    const int tid        = threadIdx.x;            // vec within row
    const int base_token = blockIdx.x * TOKENS_PER_CTA;

    // One 128-bit load fetches all 4 indices for this CTA.
    const int4 rows4 = __ldg(&idx4[blockIdx.x]);
    const int rows[TOKENS_PER_CTA] = {rows4.x, rows4.y, rows4.z, rows4.w};

    // Front-batched independent gathers (MLP=4), L2-only caching.
    float4 v[TOKENS_PER_CTA];
#pragma unroll
    for (int k = 0; k < TOKENS_PER_CTA; k++) {
        const float4* p = weight + (long long)rows[k] * VEC_PER_ROW + tid;
        asm volatile("ld.global.cg.v4.f32 {%0,%1,%2,%3}, [%4];"
                     : "=f"(v[k].x), "=f"(v[k].y), "=f"(v[k].z), "=f"(v[k].w)
                     : "l"(p));
    }

#pragma unroll
    for (int k = 0; k < TOKENS_PER_CTA; k++)
        out[(long long)(base_token + k) * VEC_PER_ROW + tid] = v[k];
}

extern "C" void kernel_launch(void* const* d_in, const int* in_sizes, int n_in,
                              void* d_out, int out_size)
{
    const int*   idx    = (const int*)d_in[0];    // x: [4, 2048] int32
    const float* weight = (const float*)d_in[1];  // [32000, 512] f32
    float*       out    = (float*)d_out;          // [4, 2048, 512] f32

    const int n_tokens = in_sizes[0];             // 8192
    const int n_ctas   = n_tokens / TOKENS_PER_CTA; // 2048

    embedding_gather_kernel<<<n_ctas, THREADS>>>(
        (const int4*)idx, (const float4*)weight, (float4*)out);
}

// round 10
// speedup vs baseline: 2.2059x; 1.0257x over previous
#include <cuda_runtime.h>
#include <cstdint>

// Embedding gather: out[token, :] = weight[idx[token], :]
// idx: [8192] int32, weight: [32000, 512] f32, out: [8192, 512] f32
//
// Terminal kernel — at the hardware floor. Cold-L2 compulsory-miss gather
// is capped by L2 miss-tracking recycle: 45 MSHR/LTS x 128 B x 184 LTS /
// ~1040 cyc DRAM latency = ~1.83 TB/s, mechanism-independent (verified
// vs LDG, TMA bulk, cache policies, sorted order, L2 prefetch pipeline).
// Floor = 14.7 MB unique rows / 1.83 TB/s ~= 8.0 us kernel.
//
// Shape: 128-thr CTAs, 4 tokens/CTA, grid=2048 (single wave, 16 CTA/SM).
// No smem / no barriers. Front-batched independent gathers (MLP=4),
// fully coalesced LDG.128/STG.128; idx loads are warp-broadcast.

static constexpr int VEC_PER_ROW    = 128;  // 512 f32 = 128 float4
static constexpr int TOKENS_PER_CTA = 4;
static constexpr int THREADS        = 128;

__global__ void __launch_bounds__(THREADS, 16)
embedding_gather_kernel(const int* __restrict__ idx,
                        const float4* __restrict__ weight,
                        float4* __restrict__ out)
{
    const int tid        = threadIdx.x;            // 0..127 = vec within row
    const int base_token = blockIdx.x * TOKENS_PER_CTA;

    // Independent index loads (warp-broadcast, cached).
    int rows[TOKENS_PER_CTA];
#pragma unroll
    for (int k = 0; k < TOKENS_PER_CTA; k++)
        rows[k] = __ldg(&idx[base_token + k]);

    // Front-batched independent gathers: MLP = 4 per thread.
    float4 v[TOKENS_PER_CTA];
#pragma unroll
    for (int k = 0; k < TOKENS_PER_CTA; k++)
        v[k] = __ldg(&weight[(long long)rows[k] * VEC_PER_ROW + tid]);

#pragma unroll
    for (int k = 0; k < TOKENS_PER_CTA; k++)
        out[(long long)(base_token + k) * VEC_PER_ROW + tid] = v[k];
}

extern "C" void kernel_launch(void* const* d_in, const int* in_sizes, int n_in,
                              void* d_out, int out_size)
{
    const int*   idx    = (const int*)d_in[0];    // x: [4, 2048] int32
    const float* weight = (const float*)d_in[1];  // [32000, 512] f32
    float*       out    = (float*)d_out;          // [4, 2048, 512] f32

    const int n_tokens = in_sizes[0];             // 8192
    const int n_ctas   = n_tokens / TOKENS_PER_CTA; // 2048

    embedding_gather_kernel<<<n_ctas, THREADS>>>(
        idx, (const float4*)weight, (float4*)out);
}